// round 15
// baseline (speedup 1.0000x reference)
#include <cuda_runtime.h>
#include <cuda_fp16.h>
#include <math.h>
#include <stdint.h>

#define B_ROWS   4096
#define T_LEN    256
#define NROWS    (B_ROWS * 64)
#define NFFT     24
#define FBINS    12
#define DIN      256
#define FEAT     512

// ---------------- scratch (__device__ globals; no allocs) ----------------
__device__ __half g_a1[B_ROWS * DIN];     // feats, fp16          2 MB
__device__ __half g_h2[B_ROWS * FEAT];    // hidden, fp16         4 MB
__device__ __half g_w1t[FEAT * DIN];      // W1^T fp16
__device__ __half g_w2t[FEAT * FEAT];     // W2^T fp16

// ---------------- helpers ----------------
__device__ __forceinline__ uint32_t smem_u32(const void* p) {
    uint32_t a;
    asm("{ .reg .u64 t; cvta.to.shared.u64 t, %1; cvt.u32.u64 %0, t; }"
        : "=r"(a) : "l"(p));
    return a;
}
__device__ __forceinline__ void cp16(uint32_t dst, const void* src) {
    asm volatile("cp.async.cg.shared.global [%0], [%1], 16;"
                 :: "r"(dst), "l"(src));
}
__device__ __forceinline__ void cp_commit() {
    asm volatile("cp.async.commit_group;");
}
template <int N>
__device__ __forceinline__ void cp_wait() {
    asm volatile("cp.async.wait_group %0;" :: "n"(N));
}
#define LDSM4(r, addr)                                                        \
    asm volatile("ldmatrix.sync.aligned.m8n8.x4.shared.b16 {%0,%1,%2,%3}, [%4];" \
                 : "=r"((r)[0]), "=r"((r)[1]), "=r"((r)[2]), "=r"((r)[3])     \
                 : "r"(addr))
#define MMA16816(d, a, b0, b1)                                                \
    asm volatile(                                                             \
        "mma.sync.aligned.m16n8k16.row.col.f32.f16.f16.f32 "                  \
        "{%0,%1,%2,%3}, {%4,%5,%6,%7}, {%8,%9}, {%0,%1,%2,%3};"               \
        : "+f"((d)[0]), "+f"((d)[1]), "+f"((d)[2]), "+f"((d)[3])              \
        : "r"((a)[0]), "r"((a)[1]), "r"((a)[2]), "r"((a)[3]),                 \
          "r"(b0), "r"(b1))

// packed fp32x2 helpers
__device__ __forceinline__ unsigned long long pack2(float lo, float hi) {
    unsigned long long r;
    asm("mov.b64 %0, {%1, %2};" : "=l"(r) : "f"(lo), "f"(hi));
    return r;
}
__device__ __forceinline__ void fma2(unsigned long long& d,
                                     unsigned long long a, unsigned long long b) {
    asm("fma.rn.f32x2 %0, %1, %2, %0;" : "+l"(d) : "l"(a), "l"(b));
}
__device__ __forceinline__ float2 unpack2(unsigned long long v) {
    float2 r;
    asm("mov.b64 {%0, %1}, %2;" : "=f"(r.x), "=f"(r.y) : "l"(v));
    return r;
}
__device__ __forceinline__ float gelu_exact(float v) {
    return 0.5f * v * (1.0f + erff(v * 0.70710678118654752f));
}

// ---------------------------------------------------------------------------
// Fused pre-pass:
//   blocks [0,352)        : feats, persistent, up to 3 tiles each, double-
//                           buffered cp.async prefetch (DRAM under compute)
//   blocks [352,480)      : prep W1
//   blocks [480,736)      : prep W2
// ---------------------------------------------------------------------------
#define XPAD        28                     // floats per smem row (112 B)
#define FT_BUF      (256 * XPAD)           // floats per tile buffer
#define FEATS_BLKS  352
#define PRE_SMEM    (2 * FT_BUF * 4)       // 57344 B dynamic

__device__ void feats_compute(const float* __restrict__ sX,
                              const unsigned long long* tw,
                              __half* __restrict__ a1, int tile, int t)
{
    float xs[NFFT];
#pragma unroll
    for (int i = 0; i < 6; i++) {
        float4 v = *reinterpret_cast<const float4*>(&sX[t * XPAD + i * 4]);
        xs[4*i + 0] = v.x; xs[4*i + 1] = v.y;
        xs[4*i + 2] = v.z; xs[4*i + 3] = v.w;
    }

    unsigned long long acc[FBINS];
#pragma unroll
    for (int k = 0; k < FBINS; k++) acc[k] = pack2(0.f, 0.f);
#pragma unroll
    for (int n = 0; n < NFFT; n++) {
        unsigned long long xv = pack2(xs[n], xs[n]);
#pragma unroll
        for (int k = 1; k <= FBINS; k++) {
            const int m = (k * n) % NFFT;
            fma2(acc[k-1], xv, tw[m]);
        }
    }

    float re[FBINS], im[FBINS], mag2[FBINS];
#pragma unroll
    for (int k = 0; k < FBINS; k++) {
        float2 p = unpack2(acc[k]);
        re[k] = p.x; im[k] = p.y;
        mag2[k] = p.x*p.x + p.y*p.y;
    }

    int i1 = 0; float m1 = mag2[0];
#pragma unroll
    for (int k = 1; k < FBINS; k++) if (mag2[k] > m1) { m1 = mag2[k]; i1 = k; }
    int i2 = (i1 == 0) ? 1 : 0; float m2 = mag2[i2];
#pragma unroll
    for (int k = 0; k < FBINS; k++)
        if (k != i1 && mag2[k] > m2) { m2 = mag2[k]; i2 = k; }

    float r1 = 0.f, q1 = 0.f, r2 = 0.f, q2 = 0.f;
#pragma unroll
    for (int k = 0; k < FBINS; k++) {
        if (k == i1) { r1 = re[k]; q1 = im[k]; }
        if (k == i2) { r2 = re[k]; q2 = im[k]; }
    }

    float o0 = sqrtf(m1);
    float o1 = sqrtf(m2);
    float o2 = atan2f(q1, r1);
    float o3 = atan2f(q2, r2);

    const int row = tile * 256 + t;
    const int b = row >> 6, c = row & 63;
    __half* base = a1 + (size_t)b * DIN + c * 4;
    reinterpret_cast<__half2*>(base)[0] =
        __halves2half2(__float2half_rn(o0), __float2half_rn(o1));
    reinterpret_cast<__half2*>(base)[1] =
        __halves2half2(__float2half_rn(o2), __float2half_rn(o3));
}

__device__ void prep_body(const float* __restrict__ W, __half* __restrict__ Tp,
                          int K, int N, int n0, int k0)
{
    __shared__ float sm[32][33];
    int tx = threadIdx.x & 31, ty = threadIdx.x >> 5;
#pragma unroll
    for (int i = ty; i < 32; i += 8)
        sm[i][tx] = W[(size_t)(k0 + i) * N + n0 + tx];
    __syncthreads();
#pragma unroll
    for (int r = ty; r < 32; r += 8)
        Tp[(size_t)(n0 + r) * K + k0 + tx] = __float2half_rn(sm[tx][r]);
}

__global__ __launch_bounds__(256) void pre_kernel(
    const float* __restrict__ x, __half* __restrict__ a1,
    const float* __restrict__ W1, __half* __restrict__ w1t,
    const float* __restrict__ W2, __half* __restrict__ w2t)
{
    const int bx = blockIdx.x;
    if (bx < FEATS_BLKS) {
        extern __shared__ float sX[];      // 2 tile buffers
        __shared__ float2 s_tw[NFFT];
        const int t = threadIdx.x;
        if (t < NFFT) {
            float s, c;
            sincospif((float)t / 12.0f, &s, &c);
            s_tw[t] = make_float2(c, -s);
        }

        // per-thread copy coords (6 chunks of 16 B)
        int crow[6], coff[6];
        uint32_t sdst[6];
        const uint32_t sb = smem_u32(sX);
#pragma unroll
        for (int k = 0; k < 6; k++) {
            const int c = t + k * 256;
            crow[k] = c / 6;
            coff[k] = c - crow[k] * 6;
            sdst[k] = sb + (uint32_t)((crow[k] * XPAD + coff[k] * 4) * 4);
        }

        auto issue_tile = [&](int tile, int buf) {
            const float* gx = x + (size_t)tile * 256 * T_LEN;
            const uint32_t so = buf * (FT_BUF * 4);
#pragma unroll
            for (int k = 0; k < 6; k++)
                cp16(sdst[k] + so, gx + (size_t)crow[k] * T_LEN + coff[k] * 4);
            cp_commit();
        };

        // number of tiles for this block: tiles bx, bx+352, bx+704 (< 1024)
        const int nt = (bx + 704 < 1024) ? 3 : ((bx + 352 < 1024) ? 2 : 1);

        issue_tile(bx, 0);
        __syncthreads();   // s_tw visible

        unsigned long long tw[NFFT];
#pragma unroll
        for (int m = 0; m < NFFT; m++) {
            float2 v = s_tw[m];
            tw[m] = pack2(v.x, v.y);
        }

        for (int i = 0; i < nt; i++) {
            if (i + 1 < nt) {
                issue_tile(bx + (i + 1) * FEATS_BLKS, (i + 1) & 1);
                cp_wait<1>();
            } else {
                cp_wait<0>();
            }
            __syncthreads();
            feats_compute(sX + (i & 1) * FT_BUF, tw, a1,
                          bx + i * FEATS_BLKS, t);
            __syncthreads();   // all reads done before buffer reuse
        }
    } else if (bx < FEATS_BLKS + 128) {
        const int bid = bx - FEATS_BLKS;           // W1: 16 x 8
        prep_body(W1, w1t, DIN, FEAT, (bid & 15) * 32, (bid >> 4) * 32);
    } else {
        const int bid = bx - (FEATS_BLKS + 128);   // W2: 16 x 16
        prep_body(W2, w2t, FEAT, FEAT, (bid & 15) * 32, (bid >> 4) * 32);
    }
}

// ---------------------------------------------------------------------------
// fp16 HMMA GEMM: CTA 64x128 (MxN), 256 threads, 8 warps of 32x32,
// KC=64 (4 k16 phases/stage), 3-stage cp.async ring, frag double-buffering.
// Grid (4, 64) = 256 CTAs, 2 CTAs/SM.
// ---------------------------------------------------------------------------
#define GT      256
#define KPAD    72
#define A_ROWS  64
#define B_ROWS_T 128
#define A_BYTES (A_ROWS * KPAD * 2)       // 9216
#define B_OFF   A_BYTES
#define STGB    (A_BYTES + B_ROWS_T * KPAD * 2)   // 27648
#define NSTAGE  3
#define SMEM_BYTES (NSTAGE * STGB)        // 82944

template <int KTOT, bool SPLIT_OUT>
__global__ __launch_bounds__(GT, 2) void hmma_gemm(
    const __half* __restrict__ A, const __half* __restrict__ Bt,
    const float* __restrict__ bias,
    float* __restrict__ outF, __half* __restrict__ outS)
{
    extern __shared__ __half sm[];

    const int tid  = threadIdx.x;
    const int lane = tid & 31;
    const int wid  = tid >> 5;
    const int brow = blockIdx.y * 64;
    const int bcol = blockIdx.x * 128;
    const int m0 = (wid & 1) * 32;
    const int n0 = (wid >> 1) * 32;

    const __half* gAp[2];
    const __half* gBp[4];
    uint32_t sAo[2], sBo[4];
#pragma unroll
    for (int i = 0; i < 2; i++) {
        int u = i * GT + tid;
        int r = u >> 3, ch = u & 7;
        gAp[i] = A + (size_t)(brow + r) * KTOT + ch * 8;
        sAo[i] = smem_u32(sm) + (uint32_t)(r * KPAD * 2 + ch * 16);
    }
#pragma unroll
    for (int i = 0; i < 4; i++) {
        int u = i * GT + tid;
        int r = u >> 3, ch = u & 7;
        gBp[i] = Bt + (size_t)(bcol + r) * KTOT + ch * 8;
        sBo[i] = smem_u32(sm) + B_OFF + (uint32_t)(r * KPAD * 2 + ch * 16);
    }

    auto copy_tile = [&](int kt, int slot) {
        const uint32_t so = slot * STGB;
        const int ko = kt * 64;
#pragma unroll
        for (int i = 0; i < 2; i++) cp16(sAo[i] + so, gAp[i] + ko);
#pragma unroll
        for (int i = 0; i < 4; i++) cp16(sBo[i] + so, gBp[i] + ko);
    };

    constexpr int NT = KTOT / 64;

#pragma unroll
    for (int p = 0; p < NSTAGE - 1; p++) {
        if (p < NT) copy_tile(p, p);
        cp_commit();
    }

    float c[2][4][4];
#pragma unroll
    for (int i = 0; i < 2; i++)
#pragma unroll
        for (int j = 0; j < 4; j++)
#pragma unroll
            for (int q = 0; q < 4; q++) c[i][j][q] = 0.0f;

    const int a_row = lane & 15;
    const int a_kh  = (lane >> 4) * 8;
    const int b_row = (lane & 7) + ((lane >> 4) << 3);
    const int b_kh  = ((lane >> 3) & 1) << 3;

    uint32_t aAddr[2], bAddr[2];
#pragma unroll
    for (int i = 0; i < 2; i++)
        aAddr[i] = smem_u32(&sm[(m0 + i * 16 + a_row) * KPAD + a_kh]);
#pragma unroll
    for (int j = 0; j < 2; j++)
        bAddr[j] = smem_u32(sm) + B_OFF +
                   (uint32_t)(((n0 + j * 16 + b_row) * KPAD + b_kh) * 2);

    uint32_t aF[2][2][4], bF[2][2][4];

    cp_wait<NSTAGE - 2>();
    __syncthreads();
#pragma unroll
    for (int i = 0; i < 2; i++) LDSM4(aF[0][i], aAddr[i]);
#pragma unroll
    for (int j = 0; j < 2; j++) LDSM4(bF[0][j], bAddr[j]);

    for (int kt = 0; kt < NT; kt++) {
        const uint32_t so  = (kt % NSTAGE) * STGB;
        const uint32_t so1 = ((kt + 1) % NSTAGE) * STGB;

#pragma unroll
        for (int ks = 0; ks < 4; ks++) {
            const int cb = ks & 1, nb = cb ^ 1;
            if (ks < 3) {
                const uint32_t po = so + (ks + 1) * 32;
#pragma unroll
                for (int i = 0; i < 2; i++) LDSM4(aF[nb][i], aAddr[i] + po);
#pragma unroll
                for (int j = 0; j < 2; j++) LDSM4(bF[nb][j], bAddr[j] + po);
            }
            if (ks == 1) {
                const int nk = kt + NSTAGE - 1;
                if (nk < NT) copy_tile(nk, nk % NSTAGE);
                cp_commit();
            }
            if (ks == 3) {
                cp_wait<NSTAGE - 2>();
                __syncthreads();
            }
#pragma unroll
            for (int i = 0; i < 2; i++)
#pragma unroll
                for (int jn = 0; jn < 4; jn++) {
                    const int j = jn >> 1;
                    if (jn & 1) MMA16816(c[i][jn], aF[cb][i], bF[cb][j][2], bF[cb][j][3]);
                    else        MMA16816(c[i][jn], aF[cb][i], bF[cb][j][0], bF[cb][j][1]);
                }
        }

        if (kt + 1 < NT) {
#pragma unroll
            for (int i = 0; i < 2; i++) LDSM4(aF[0][i], aAddr[i] + so1);
#pragma unroll
            for (int j = 0; j < 2; j++) LDSM4(bF[0][j], bAddr[j] + so1);
        }
    }

    // ---- epilogue ----
#pragma unroll
    for (int i = 0; i < 2; i++) {
        const int gm = brow + m0 + i * 16 + (lane >> 2);
#pragma unroll
        for (int jn = 0; jn < 4; jn++) {
            const int gc = bcol + n0 + jn * 8 + ((lane & 3) << 1);
            float2 bb = *reinterpret_cast<const float2*>(bias + gc);
#pragma unroll
            for (int rh = 0; rh < 2; rh++) {
                const int m = gm + rh * 8;
                float v0 = c[i][jn][rh * 2 + 0] + bb.x;
                float v1 = c[i][jn][rh * 2 + 1] + bb.y;
                if (SPLIT_OUT) {
                    v0 = gelu_exact(v0);
                    v1 = gelu_exact(v1);
                    *reinterpret_cast<__half2*>(outS + (size_t)m * FEAT + gc) =
                        __halves2half2(__float2half_rn(v0), __float2half_rn(v1));
                } else {
                    float2 o{v0, v1};
                    *reinterpret_cast<float2*>(outF + (size_t)m * FEAT + gc) = o;
                }
            }
        }
    }
}

// ---------------------------------------------------------------------------
extern "C" void kernel_launch(void* const* d_in, const int* in_sizes, int n_in,
                              void* d_out, int out_size)
{
    const float* x  = (const float*)d_in[0];
    const float* W1 = (const float*)d_in[1];
    const float* b1 = (const float*)d_in[2];
    const float* W2 = (const float*)d_in[3];
    const float* b2 = (const float*)d_in[4];
    float* out = (float*)d_out;

    __half *a1, *h2, *w1t, *w2t;
    cudaGetSymbolAddress((void**)&a1,  g_a1);
    cudaGetSymbolAddress((void**)&h2,  g_h2);
    cudaGetSymbolAddress((void**)&w1t, g_w1t);
    cudaGetSymbolAddress((void**)&w2t, g_w2t);

    cudaFuncSetAttribute(pre_kernel,
                         cudaFuncAttributeMaxDynamicSharedMemorySize, PRE_SMEM);
    cudaFuncSetAttribute(hmma_gemm<DIN, true>,
                         cudaFuncAttributeMaxDynamicSharedMemorySize, SMEM_BYTES);
    cudaFuncSetAttribute(hmma_gemm<FEAT, false>,
                         cudaFuncAttributeMaxDynamicSharedMemorySize, SMEM_BYTES);

    pre_kernel<<<FEATS_BLKS + 128 + 256, 256, PRE_SMEM>>>(
        x, a1, W1, w1t, W2, w2t);

    dim3 grid(FEAT / 128, B_ROWS / 64);   // (4, 64) = 256 CTAs, 2/SM
    hmma_gemm<DIN,  true ><<<grid, GT, SMEM_BYTES>>>(a1, w1t, b1, nullptr, h2);
    hmma_gemm<FEAT, false><<<grid, GT, SMEM_BYTES>>>(h2, w2t, b2, out, nullptr);
}

// round 16
// speedup vs baseline: 1.0618x; 1.0618x over previous
#include <cuda_runtime.h>
#include <cuda_fp16.h>
#include <math.h>
#include <stdint.h>

#define B_ROWS   4096
#define T_LEN    256
#define NROWS    (B_ROWS * 64)
#define NFFT     24
#define FBINS    12
#define DIN      256
#define FEAT     512

// ---------------- scratch (__device__ globals; no allocs) ----------------
__device__ __half g_a1[B_ROWS * DIN];     // feats, fp16          2 MB
__device__ __half g_h2[B_ROWS * FEAT];    // hidden, fp16         4 MB
__device__ __half g_w1t[FEAT * DIN];      // W1^T fp16
__device__ __half g_w2t[FEAT * FEAT];     // W2^T fp16

// ---------------- helpers ----------------
__device__ __forceinline__ uint32_t smem_u32(const void* p) {
    uint32_t a;
    asm("{ .reg .u64 t; cvta.to.shared.u64 t, %1; cvt.u32.u64 %0, t; }"
        : "=r"(a) : "l"(p));
    return a;
}
__device__ __forceinline__ void cp16(uint32_t dst, const void* src) {
    asm volatile("cp.async.cg.shared.global [%0], [%1], 16;"
                 :: "r"(dst), "l"(src));
}
__device__ __forceinline__ void cp_commit() {
    asm volatile("cp.async.commit_group;");
}
template <int N>
__device__ __forceinline__ void cp_wait() {
    asm volatile("cp.async.wait_group %0;" :: "n"(N));
}
#define LDSM4(r, addr)                                                        \
    asm volatile("ldmatrix.sync.aligned.m8n8.x4.shared.b16 {%0,%1,%2,%3}, [%4];" \
                 : "=r"((r)[0]), "=r"((r)[1]), "=r"((r)[2]), "=r"((r)[3])     \
                 : "r"(addr))
#define MMA16816(d, a, b0, b1)                                                \
    asm volatile(                                                             \
        "mma.sync.aligned.m16n8k16.row.col.f32.f16.f16.f32 "                  \
        "{%0,%1,%2,%3}, {%4,%5,%6,%7}, {%8,%9}, {%0,%1,%2,%3};"               \
        : "+f"((d)[0]), "+f"((d)[1]), "+f"((d)[2]), "+f"((d)[3])              \
        : "r"((a)[0]), "r"((a)[1]), "r"((a)[2]), "r"((a)[3]),                 \
          "r"(b0), "r"(b1))

// packed fp32x2 helpers
__device__ __forceinline__ unsigned long long pack2(float lo, float hi) {
    unsigned long long r;
    asm("mov.b64 %0, {%1, %2};" : "=l"(r) : "f"(lo), "f"(hi));
    return r;
}
__device__ __forceinline__ void fma2(unsigned long long& d,
                                     unsigned long long a, unsigned long long b) {
    asm("fma.rn.f32x2 %0, %1, %2, %0;" : "+l"(d) : "l"(a), "l"(b));
}
__device__ __forceinline__ float2 unpack2(unsigned long long v) {
    float2 r;
    asm("mov.b64 {%0, %1}, %2;" : "=f"(r.x), "=f"(r.y) : "l"(v));
    return r;
}
__device__ __forceinline__ float gelu_exact(float v) {
    return 0.5f * v * (1.0f + erff(v * 0.70710678118654752f));
}

// ---------------------------------------------------------------------------
// Fused pre-pass:
//   blocks [0,352)   : feats, persistent, up to 3 tiles, double-buffered
//   blocks [352,480) : prep W1        blocks [480,736) : prep W2
// ---------------------------------------------------------------------------
#define XPAD        28                     // floats per smem row (112 B)
#define FT_BUF      (256 * XPAD)
#define FEATS_BLKS  352
#define PRE_SMEM    (2 * FT_BUF * 4)       // 57344 B dynamic

__device__ void feats_compute(const float* __restrict__ sX,
                              const unsigned long long* tw,
                              __half* __restrict__ a1, int tile, int t)
{
    float xs[NFFT];
#pragma unroll
    for (int i = 0; i < 6; i++) {
        float4 v = *reinterpret_cast<const float4*>(&sX[t * XPAD + i * 4]);
        xs[4*i + 0] = v.x; xs[4*i + 1] = v.y;
        xs[4*i + 2] = v.z; xs[4*i + 3] = v.w;
    }

    // radix-2 fold: X[k] = sum_{n<12} (k even ? x[n]+x[n+12] : x[n]-x[n+12]) w^{kn}
    unsigned long long ev[12], od[12];
#pragma unroll
    for (int n = 0; n < 12; n++) {
        float e = xs[n] + xs[n + 12];
        float o = xs[n] - xs[n + 12];
        ev[n] = pack2(e, e);
        od[n] = pack2(o, o);
    }

    unsigned long long acc[FBINS];
#pragma unroll
    for (int k = 0; k < FBINS; k++) acc[k] = pack2(0.f, 0.f);
#pragma unroll
    for (int n = 0; n < 12; n++) {
#pragma unroll
        for (int k = 1; k <= FBINS; k++) {
            const int m = (k * n) % NFFT;          // compile-time constant
            if (k & 1) fma2(acc[k-1], od[n], tw[m]);
            else       fma2(acc[k-1], ev[n], tw[m]);
        }
    }

    float re[FBINS], im[FBINS], mag2[FBINS];
#pragma unroll
    for (int k = 0; k < FBINS; k++) {
        float2 p = unpack2(acc[k]);
        re[k] = p.x; im[k] = p.y;
        mag2[k] = p.x*p.x + p.y*p.y;
    }

    int i1 = 0; float m1 = mag2[0];
#pragma unroll
    for (int k = 1; k < FBINS; k++) if (mag2[k] > m1) { m1 = mag2[k]; i1 = k; }
    int i2 = (i1 == 0) ? 1 : 0; float m2 = mag2[i2];
#pragma unroll
    for (int k = 0; k < FBINS; k++)
        if (k != i1 && mag2[k] > m2) { m2 = mag2[k]; i2 = k; }

    float r1 = 0.f, q1 = 0.f, r2 = 0.f, q2 = 0.f;
#pragma unroll
    for (int k = 0; k < FBINS; k++) {
        if (k == i1) { r1 = re[k]; q1 = im[k]; }
        if (k == i2) { r2 = re[k]; q2 = im[k]; }
    }

    float o0 = sqrtf(m1);
    float o1 = sqrtf(m2);
    float o2 = atan2f(q1, r1);
    float o3 = atan2f(q2, r2);

    const int row = tile * 256 + t;
    const int b = row >> 6, c = row & 63;
    __half* base = a1 + (size_t)b * DIN + c * 4;
    reinterpret_cast<__half2*>(base)[0] =
        __halves2half2(__float2half_rn(o0), __float2half_rn(o1));
    reinterpret_cast<__half2*>(base)[1] =
        __halves2half2(__float2half_rn(o2), __float2half_rn(o3));
}

__device__ void prep_body(const float* __restrict__ W, __half* __restrict__ Tp,
                          int K, int N, int n0, int k0)
{
    __shared__ float sm[32][33];
    int tx = threadIdx.x & 31, ty = threadIdx.x >> 5;
#pragma unroll
    for (int i = ty; i < 32; i += 8)
        sm[i][tx] = W[(size_t)(k0 + i) * N + n0 + tx];
    __syncthreads();
#pragma unroll
    for (int r = ty; r < 32; r += 8)
        Tp[(size_t)(n0 + r) * K + k0 + tx] = __float2half_rn(sm[tx][r]);
}

__global__ __launch_bounds__(256) void pre_kernel(
    const float* __restrict__ x, __half* __restrict__ a1,
    const float* __restrict__ W1, __half* __restrict__ w1t,
    const float* __restrict__ W2, __half* __restrict__ w2t)
{
    const int bx = blockIdx.x;
    if (bx < FEATS_BLKS) {
        extern __shared__ float sX[];
        __shared__ float2 s_tw[NFFT];
        const int t = threadIdx.x;
        if (t < NFFT) {
            float s, c;
            sincospif((float)t / 12.0f, &s, &c);
            s_tw[t] = make_float2(c, -s);
        }

        int crow[6], coff[6];
        uint32_t sdst[6];
        const uint32_t sb = smem_u32(sX);
#pragma unroll
        for (int k = 0; k < 6; k++) {
            const int c = t + k * 256;
            crow[k] = c / 6;
            coff[k] = c - crow[k] * 6;
            sdst[k] = sb + (uint32_t)((crow[k] * XPAD + coff[k] * 4) * 4);
        }

        auto issue_tile = [&](int tile, int buf) {
            const float* gx = x + (size_t)tile * 256 * T_LEN;
            const uint32_t so = buf * (FT_BUF * 4);
#pragma unroll
            for (int k = 0; k < 6; k++)
                cp16(sdst[k] + so, gx + (size_t)crow[k] * T_LEN + coff[k] * 4);
            cp_commit();
        };

        const int nt = (bx + 704 < 1024) ? 3 : ((bx + 352 < 1024) ? 2 : 1);

        issue_tile(bx, 0);
        __syncthreads();

        unsigned long long tw[NFFT];
#pragma unroll
        for (int m = 0; m < NFFT; m++) {
            float2 v = s_tw[m];
            tw[m] = pack2(v.x, v.y);
        }

        for (int i = 0; i < nt; i++) {
            if (i + 1 < nt) {
                issue_tile(bx + (i + 1) * FEATS_BLKS, (i + 1) & 1);
                cp_wait<1>();
            } else {
                cp_wait<0>();
            }
            __syncthreads();
            feats_compute(sX + (i & 1) * FT_BUF, tw, a1,
                          bx + i * FEATS_BLKS, t);
            __syncthreads();
        }
    } else if (bx < FEATS_BLKS + 128) {
        const int bid = bx - FEATS_BLKS;
        prep_body(W1, w1t, DIN, FEAT, (bid & 15) * 32, (bid >> 4) * 32);
    } else {
        const int bid = bx - (FEATS_BLKS + 128);
        prep_body(W2, w2t, FEAT, FEAT, (bid & 15) * 32, (bid >> 4) * 32);
    }
}

// ---------------------------------------------------------------------------
// fp16 HMMA GEMM: CTA 64x128 (MxN), 256 threads, 8 warps of 32x32,
// KC=64 (4 k16 phases/stage), 3-stage cp.async ring, frag double-buffering.
// Grid (4, 64) = 256 CTAs, 2 CTAs/SM.
// ---------------------------------------------------------------------------
#define GT      256
#define KPAD    72
#define A_ROWS  64
#define B_ROWS_T 128
#define A_BYTES (A_ROWS * KPAD * 2)       // 9216
#define B_OFF   A_BYTES
#define STGB    (A_BYTES + B_ROWS_T * KPAD * 2)   // 27648
#define NSTAGE  3
#define SMEM_BYTES (NSTAGE * STGB)        // 82944

template <int KTOT, bool SPLIT_OUT>
__global__ __launch_bounds__(GT, 2) void hmma_gemm(
    const __half* __restrict__ A, const __half* __restrict__ Bt,
    const float* __restrict__ bias,
    float* __restrict__ outF, __half* __restrict__ outS)
{
    extern __shared__ __half sm[];

    const int tid  = threadIdx.x;
    const int lane = tid & 31;
    const int wid  = tid >> 5;
    const int brow = blockIdx.y * 64;
    const int bcol = blockIdx.x * 128;
    const int m0 = (wid & 1) * 32;
    const int n0 = (wid >> 1) * 32;

    const __half* gAp[2];
    const __half* gBp[4];
    uint32_t sAo[2], sBo[4];
#pragma unroll
    for (int i = 0; i < 2; i++) {
        int u = i * GT + tid;
        int r = u >> 3, ch = u & 7;
        gAp[i] = A + (size_t)(brow + r) * KTOT + ch * 8;
        sAo[i] = smem_u32(sm) + (uint32_t)(r * KPAD * 2 + ch * 16);
    }
#pragma unroll
    for (int i = 0; i < 4; i++) {
        int u = i * GT + tid;
        int r = u >> 3, ch = u & 7;
        gBp[i] = Bt + (size_t)(bcol + r) * KTOT + ch * 8;
        sBo[i] = smem_u32(sm) + B_OFF + (uint32_t)(r * KPAD * 2 + ch * 16);
    }

    auto copy_tile = [&](int kt, int slot) {
        const uint32_t so = slot * STGB;
        const int ko = kt * 64;
#pragma unroll
        for (int i = 0; i < 2; i++) cp16(sAo[i] + so, gAp[i] + ko);
#pragma unroll
        for (int i = 0; i < 4; i++) cp16(sBo[i] + so, gBp[i] + ko);
    };

    constexpr int NT = KTOT / 64;

#pragma unroll
    for (int p = 0; p < NSTAGE - 1; p++) {
        if (p < NT) copy_tile(p, p);
        cp_commit();
    }

    float c[2][4][4];
#pragma unroll
    for (int i = 0; i < 2; i++)
#pragma unroll
        for (int j = 0; j < 4; j++)
#pragma unroll
            for (int q = 0; q < 4; q++) c[i][j][q] = 0.0f;

    const int a_row = lane & 15;
    const int a_kh  = (lane >> 4) * 8;
    const int b_row = (lane & 7) + ((lane >> 4) << 3);
    const int b_kh  = ((lane >> 3) & 1) << 3;

    uint32_t aAddr[2], bAddr[2];
#pragma unroll
    for (int i = 0; i < 2; i++)
        aAddr[i] = smem_u32(&sm[(m0 + i * 16 + a_row) * KPAD + a_kh]);
#pragma unroll
    for (int j = 0; j < 2; j++)
        bAddr[j] = smem_u32(sm) + B_OFF +
                   (uint32_t)(((n0 + j * 16 + b_row) * KPAD + b_kh) * 2);

    uint32_t aF[2][2][4], bF[2][2][4];

    cp_wait<NSTAGE - 2>();
    __syncthreads();
#pragma unroll
    for (int i = 0; i < 2; i++) LDSM4(aF[0][i], aAddr[i]);
#pragma unroll
    for (int j = 0; j < 2; j++) LDSM4(bF[0][j], bAddr[j]);

    for (int kt = 0; kt < NT; kt++) {
        const uint32_t so  = (kt % NSTAGE) * STGB;
        const uint32_t so1 = ((kt + 1) % NSTAGE) * STGB;

#pragma unroll
        for (int ks = 0; ks < 4; ks++) {
            const int cb = ks & 1, nb = cb ^ 1;
            if (ks < 3) {
                const uint32_t po = so + (ks + 1) * 32;
#pragma unroll
                for (int i = 0; i < 2; i++) LDSM4(aF[nb][i], aAddr[i] + po);
#pragma unroll
                for (int j = 0; j < 2; j++) LDSM4(bF[nb][j], bAddr[j] + po);
            }
            if (ks == 1) {
                const int nk = kt + NSTAGE - 1;
                if (nk < NT) copy_tile(nk, nk % NSTAGE);
                cp_commit();
            }
            if (ks == 3) {
                cp_wait<NSTAGE - 2>();
                __syncthreads();
            }
#pragma unroll
            for (int i = 0; i < 2; i++)
#pragma unroll
                for (int jn = 0; jn < 4; jn++) {
                    const int j = jn >> 1;
                    if (jn & 1) MMA16816(c[i][jn], aF[cb][i], bF[cb][j][2], bF[cb][j][3]);
                    else        MMA16816(c[i][jn], aF[cb][i], bF[cb][j][0], bF[cb][j][1]);
                }
        }

        if (kt + 1 < NT) {
#pragma unroll
            for (int i = 0; i < 2; i++) LDSM4(aF[0][i], aAddr[i] + so1);
#pragma unroll
            for (int j = 0; j < 2; j++) LDSM4(bF[0][j], bAddr[j] + so1);
        }
    }

    // ---- epilogue ----
#pragma unroll
    for (int i = 0; i < 2; i++) {
        const int gm = brow + m0 + i * 16 + (lane >> 2);
#pragma unroll
        for (int jn = 0; jn < 4; jn++) {
            const int gc = bcol + n0 + jn * 8 + ((lane & 3) << 1);
            float2 bb = *reinterpret_cast<const float2*>(bias + gc);
#pragma unroll
            for (int rh = 0; rh < 2; rh++) {
                const int m = gm + rh * 8;
                float v0 = c[i][jn][rh * 2 + 0] + bb.x;
                float v1 = c[i][jn][rh * 2 + 1] + bb.y;
                if (SPLIT_OUT) {
                    v0 = gelu_exact(v0);
                    v1 = gelu_exact(v1);
                    *reinterpret_cast<__half2*>(outS + (size_t)m * FEAT + gc) =
                        __halves2half2(__float2half_rn(v0), __float2half_rn(v1));
                } else {
                    float2 o{v0, v1};
                    *reinterpret_cast<float2*>(outF + (size_t)m * FEAT + gc) = o;
                }
            }
        }
    }
}

// ---------------------------------------------------------------------------
extern "C" void kernel_launch(void* const* d_in, const int* in_sizes, int n_in,
                              void* d_out, int out_size)
{
    const float* x  = (const float*)d_in[0];
    const float* W1 = (const float*)d_in[1];
    const float* b1 = (const float*)d_in[2];
    const float* W2 = (const float*)d_in[3];
    const float* b2 = (const float*)d_in[4];
    float* out = (float*)d_out;

    __half *a1, *h2, *w1t, *w2t;
    cudaGetSymbolAddress((void**)&a1,  g_a1);
    cudaGetSymbolAddress((void**)&h2,  g_h2);
    cudaGetSymbolAddress((void**)&w1t, g_w1t);
    cudaGetSymbolAddress((void**)&w2t, g_w2t);

    cudaFuncSetAttribute(pre_kernel,
                         cudaFuncAttributeMaxDynamicSharedMemorySize, PRE_SMEM);
    cudaFuncSetAttribute(hmma_gemm<DIN, true>,
                         cudaFuncAttributeMaxDynamicSharedMemorySize, SMEM_BYTES);
    cudaFuncSetAttribute(hmma_gemm<FEAT, false>,
                         cudaFuncAttributeMaxDynamicSharedMemorySize, SMEM_BYTES);

    pre_kernel<<<FEATS_BLKS + 128 + 256, 256, PRE_SMEM>>>(
        x, a1, W1, w1t, W2, w2t);

    dim3 grid(FEAT / 128, B_ROWS / 64);   // (4, 64) = 256 CTAs, 2/SM
    hmma_gemm<DIN,  true ><<<grid, GT, SMEM_BYTES>>>(a1, w1t, b1, nullptr, h2);
    hmma_gemm<FEAT, false><<<grid, GT, SMEM_BYTES>>>(h2, w2t, b2, out, nullptr);
}

// round 17
// speedup vs baseline: 1.1250x; 1.0596x over previous
#include <cuda_runtime.h>
#include <cuda_fp16.h>
#include <math.h>
#include <stdint.h>

#define B_ROWS   4096
#define T_LEN    256
#define NROWS    (B_ROWS * 64)
#define NFFT     24
#define FBINS    12
#define DIN      256
#define FEAT     512

// ---------------- scratch (__device__ globals; no allocs) ----------------
__device__ __half g_a1[B_ROWS * DIN];     // feats, fp16          2 MB
__device__ __half g_h2[B_ROWS * FEAT];    // hidden, fp16         4 MB
__device__ __half g_w1t[FEAT * DIN];      // W1^T fp16
__device__ __half g_w2t[FEAT * FEAT];     // W2^T fp16

// ---------------- helpers ----------------
__device__ __forceinline__ uint32_t smem_u32(const void* p) {
    uint32_t a;
    asm("{ .reg .u64 t; cvta.to.shared.u64 t, %1; cvt.u32.u64 %0, t; }"
        : "=r"(a) : "l"(p));
    return a;
}
__device__ __forceinline__ void cp16(uint32_t dst, const void* src) {
    asm volatile("cp.async.cg.shared.global [%0], [%1], 16;"
                 :: "r"(dst), "l"(src));
}
__device__ __forceinline__ void cp_commit() {
    asm volatile("cp.async.commit_group;");
}
template <int N>
__device__ __forceinline__ void cp_wait() {
    asm volatile("cp.async.wait_group %0;" :: "n"(N));
}
#define LDSM4(r, addr)                                                        \
    asm volatile("ldmatrix.sync.aligned.m8n8.x4.shared.b16 {%0,%1,%2,%3}, [%4];" \
                 : "=r"((r)[0]), "=r"((r)[1]), "=r"((r)[2]), "=r"((r)[3])     \
                 : "r"(addr))
#define MMA16816(d, a, b0, b1)                                                \
    asm volatile(                                                             \
        "mma.sync.aligned.m16n8k16.row.col.f32.f16.f16.f32 "                  \
        "{%0,%1,%2,%3}, {%4,%5,%6,%7}, {%8,%9}, {%0,%1,%2,%3};"               \
        : "+f"((d)[0]), "+f"((d)[1]), "+f"((d)[2]), "+f"((d)[3])              \
        : "r"((a)[0]), "r"((a)[1]), "r"((a)[2]), "r"((a)[3]),                 \
          "r"(b0), "r"(b1))

// packed fp32x2 helpers
__device__ __forceinline__ unsigned long long pack2(float lo, float hi) {
    unsigned long long r;
    asm("mov.b64 %0, {%1, %2};" : "=l"(r) : "f"(lo), "f"(hi));
    return r;
}
__device__ __forceinline__ void fma2(unsigned long long& d,
                                     unsigned long long a, unsigned long long b) {
    asm("fma.rn.f32x2 %0, %1, %2, %0;" : "+l"(d) : "l"(a), "l"(b));
}
__device__ __forceinline__ float2 unpack2(unsigned long long v) {
    float2 r;
    asm("mov.b64 {%0, %1}, %2;" : "=f"(r.x), "=f"(r.y) : "l"(v));
    return r;
}
__device__ __forceinline__ float gelu_exact(float v) {
    return 0.5f * v * (1.0f + erff(v * 0.70710678118654752f));
}

// fast atan2: |err| <= ~1e-5 rad (A&S 4.4.49 minimax), far below fp16 ULP.
__device__ __forceinline__ float fast_atan2(float y, float x) {
    float ax = fabsf(x), ay = fabsf(y);
    float mx = fmaxf(ax, ay), mn = fminf(ax, ay);
    float r  = __fdividef(mn, fmaxf(mx, 1e-35f));
    float r2 = r * r;
    float p = fmaf(r2,  0.0208351f, -0.085133f);
    p = fmaf(r2, p,  0.180141f);
    p = fmaf(r2, p, -0.3302995f);
    p = fmaf(r2, p,  0.999866f);
    float a = p * r;
    if (ay > ax) a = 1.57079632679f - a;
    if (x < 0.0f) a = 3.14159265359f - a;
    return copysignf(a, y);
}
__device__ __forceinline__ float fast_sqrt(float m) {
    return (m > 0.0f) ? m * rsqrtf(m) : 0.0f;
}

// ---------------------------------------------------------------------------
// Fused pre-pass:
//   blocks [0,352)   : feats, persistent, up to 3 tiles, double-buffered
//   blocks [352,480) : prep W1        blocks [480,736) : prep W2
// ---------------------------------------------------------------------------
#define XPAD        28                     // floats per smem row (112 B)
#define FT_BUF      (256 * XPAD)
#define FEATS_BLKS  352
#define PRE_SMEM    (2 * FT_BUF * 4)       // 57344 B dynamic

__device__ void feats_compute(const float* __restrict__ sX,
                              const unsigned long long* tw,
                              __half* __restrict__ a1, int tile, int t)
{
    float xs[NFFT];
#pragma unroll
    for (int i = 0; i < 6; i++) {
        float4 v = *reinterpret_cast<const float4*>(&sX[t * XPAD + i * 4]);
        xs[4*i + 0] = v.x; xs[4*i + 1] = v.y;
        xs[4*i + 2] = v.z; xs[4*i + 3] = v.w;
    }

    // radix-2 fold #1: e[n]=x[n]+x[n+12], o[n]=x[n]-x[n+12]  (n<12)
    //   odd k :  X[k] = sum_{n<12} o[n] w^{kn}
    // radix-2 fold #2 on e (even k=2j):
    //   j even:  ee[n]=e[n]+e[n+6],  X[2j]=sum_{n<6} ee[n] w^{2jn}
    //   j odd :  eo[n]=e[n]-e[n+6],  X[2j]=sum_{n<6} eo[n] w^{2jn}
    float e[12], o[12];
#pragma unroll
    for (int n = 0; n < 12; n++) {
        e[n] = xs[n] + xs[n + 12];
        o[n] = xs[n] - xs[n + 12];
    }
    unsigned long long od[12], pee[6], peo[6];
#pragma unroll
    for (int n = 0; n < 12; n++) od[n] = pack2(o[n], o[n]);
#pragma unroll
    for (int n = 0; n < 6; n++) {
        float a = e[n] + e[n + 6];
        float b = e[n] - e[n + 6];
        pee[n] = pack2(a, a);
        peo[n] = pack2(b, b);
    }

    unsigned long long acc[FBINS];
#pragma unroll
    for (int k = 0; k < FBINS; k++) acc[k] = pack2(0.f, 0.f);
    // odd bins: k = 1,3,5,7,9,11
#pragma unroll
    for (int n = 0; n < 12; n++) {
#pragma unroll
        for (int k = 1; k <= FBINS; k += 2) {
            const int m = (k * n) % NFFT;
            fma2(acc[k-1], od[n], tw[m]);
        }
    }
    // even bins: k = 2,6,10 (eo) and k = 4,8,12 (ee)
#pragma unroll
    for (int n = 0; n < 6; n++) {
#pragma unroll
        for (int k = 2; k <= FBINS; k += 2) {
            const int m = (k * n) % NFFT;
            if ((k >> 1) & 1) fma2(acc[k-1], peo[n], tw[m]);
            else              fma2(acc[k-1], pee[n], tw[m]);
        }
    }

    float re[FBINS], im[FBINS], mag2[FBINS];
#pragma unroll
    for (int k = 0; k < FBINS; k++) {
        float2 p = unpack2(acc[k]);
        re[k] = p.x; im[k] = p.y;
        mag2[k] = p.x*p.x + p.y*p.y;
    }

    int i1 = 0; float m1 = mag2[0];
#pragma unroll
    for (int k = 1; k < FBINS; k++) if (mag2[k] > m1) { m1 = mag2[k]; i1 = k; }
    int i2 = (i1 == 0) ? 1 : 0; float m2 = mag2[i2];
#pragma unroll
    for (int k = 0; k < FBINS; k++)
        if (k != i1 && mag2[k] > m2) { m2 = mag2[k]; i2 = k; }

    float r1 = 0.f, q1 = 0.f, r2 = 0.f, q2 = 0.f;
#pragma unroll
    for (int k = 0; k < FBINS; k++) {
        if (k == i1) { r1 = re[k]; q1 = im[k]; }
        if (k == i2) { r2 = re[k]; q2 = im[k]; }
    }

    float o0 = fast_sqrt(m1);
    float o1 = fast_sqrt(m2);
    float o2 = fast_atan2(q1, r1);
    float o3 = fast_atan2(q2, r2);

    const int row = tile * 256 + t;
    const int b = row >> 6, c = row & 63;
    __half* base = a1 + (size_t)b * DIN + c * 4;
    reinterpret_cast<__half2*>(base)[0] =
        __halves2half2(__float2half_rn(o0), __float2half_rn(o1));
    reinterpret_cast<__half2*>(base)[1] =
        __halves2half2(__float2half_rn(o2), __float2half_rn(o3));
}

__device__ void prep_body(const float* __restrict__ W, __half* __restrict__ Tp,
                          int K, int N, int n0, int k0)
{
    __shared__ float sm[32][33];
    int tx = threadIdx.x & 31, ty = threadIdx.x >> 5;
#pragma unroll
    for (int i = ty; i < 32; i += 8)
        sm[i][tx] = W[(size_t)(k0 + i) * N + n0 + tx];
    __syncthreads();
#pragma unroll
    for (int r = ty; r < 32; r += 8)
        Tp[(size_t)(n0 + r) * K + k0 + tx] = __float2half_rn(sm[tx][r]);
}

__global__ __launch_bounds__(256) void pre_kernel(
    const float* __restrict__ x, __half* __restrict__ a1,
    const float* __restrict__ W1, __half* __restrict__ w1t,
    const float* __restrict__ W2, __half* __restrict__ w2t)
{
    const int bx = blockIdx.x;
    if (bx < FEATS_BLKS) {
        extern __shared__ float sX[];
        __shared__ float2 s_tw[NFFT];
        const int t = threadIdx.x;
        if (t < NFFT) {
            float s, c;
            sincospif((float)t / 12.0f, &s, &c);
            s_tw[t] = make_float2(c, -s);
        }

        int crow[6], coff[6];
        uint32_t sdst[6];
        const uint32_t sb = smem_u32(sX);
#pragma unroll
        for (int k = 0; k < 6; k++) {
            const int c = t + k * 256;
            crow[k] = c / 6;
            coff[k] = c - crow[k] * 6;
            sdst[k] = sb + (uint32_t)((crow[k] * XPAD + coff[k] * 4) * 4);
        }

        auto issue_tile = [&](int tile, int buf) {
            const float* gx = x + (size_t)tile * 256 * T_LEN;
            const uint32_t so = buf * (FT_BUF * 4);
#pragma unroll
            for (int k = 0; k < 6; k++)
                cp16(sdst[k] + so, gx + (size_t)crow[k] * T_LEN + coff[k] * 4);
            cp_commit();
        };

        const int nt = (bx + 704 < 1024) ? 3 : ((bx + 352 < 1024) ? 2 : 1);

        issue_tile(bx, 0);
        __syncthreads();

        unsigned long long tw[NFFT];
#pragma unroll
        for (int m = 0; m < NFFT; m++) {
            float2 v = s_tw[m];
            tw[m] = pack2(v.x, v.y);
        }

        for (int i = 0; i < nt; i++) {
            if (i + 1 < nt) {
                issue_tile(bx + (i + 1) * FEATS_BLKS, (i + 1) & 1);
                cp_wait<1>();
            } else {
                cp_wait<0>();
            }
            __syncthreads();
            feats_compute(sX + (i & 1) * FT_BUF, tw, a1,
                          bx + i * FEATS_BLKS, t);
            __syncthreads();
        }
    } else if (bx < FEATS_BLKS + 128) {
        const int bid = bx - FEATS_BLKS;
        prep_body(W1, w1t, DIN, FEAT, (bid & 15) * 32, (bid >> 4) * 32);
    } else {
        const int bid = bx - (FEATS_BLKS + 128);
        prep_body(W2, w2t, FEAT, FEAT, (bid & 15) * 32, (bid >> 4) * 32);
    }
}

// ---------------------------------------------------------------------------
// fp16 HMMA GEMM: CTA 64x128 (MxN), 256 threads, 8 warps of 32x32,
// KC=64 (4 k16 phases/stage), 3-stage cp.async ring, frag double-buffering.
// Grid (4, 64) = 256 CTAs, 2 CTAs/SM.
// ---------------------------------------------------------------------------
#define GT      256
#define KPAD    72
#define A_ROWS  64
#define B_ROWS_T 128
#define A_BYTES (A_ROWS * KPAD * 2)       // 9216
#define B_OFF   A_BYTES
#define STGB    (A_BYTES + B_ROWS_T * KPAD * 2)   // 27648
#define NSTAGE  3
#define SMEM_BYTES (NSTAGE * STGB)        // 82944

template <int KTOT, bool SPLIT_OUT>
__global__ __launch_bounds__(GT, 2) void hmma_gemm(
    const __half* __restrict__ A, const __half* __restrict__ Bt,
    const float* __restrict__ bias,
    float* __restrict__ outF, __half* __restrict__ outS)
{
    extern __shared__ __half sm[];

    const int tid  = threadIdx.x;
    const int lane = tid & 31;
    const int wid  = tid >> 5;
    const int brow = blockIdx.y * 64;
    const int bcol = blockIdx.x * 128;
    const int m0 = (wid & 1) * 32;
    const int n0 = (wid >> 1) * 32;

    const __half* gAp[2];
    const __half* gBp[4];
    uint32_t sAo[2], sBo[4];
#pragma unroll
    for (int i = 0; i < 2; i++) {
        int u = i * GT + tid;
        int r = u >> 3, ch = u & 7;
        gAp[i] = A + (size_t)(brow + r) * KTOT + ch * 8;
        sAo[i] = smem_u32(sm) + (uint32_t)(r * KPAD * 2 + ch * 16);
    }
#pragma unroll
    for (int i = 0; i < 4; i++) {
        int u = i * GT + tid;
        int r = u >> 3, ch = u & 7;
        gBp[i] = Bt + (size_t)(bcol + r) * KTOT + ch * 8;
        sBo[i] = smem_u32(sm) + B_OFF + (uint32_t)(r * KPAD * 2 + ch * 16);
    }

    auto copy_tile = [&](int kt, int slot) {
        const uint32_t so = slot * STGB;
        const int ko = kt * 64;
#pragma unroll
        for (int i = 0; i < 2; i++) cp16(sAo[i] + so, gAp[i] + ko);
#pragma unroll
        for (int i = 0; i < 4; i++) cp16(sBo[i] + so, gBp[i] + ko);
    };

    constexpr int NT = KTOT / 64;

#pragma unroll
    for (int p = 0; p < NSTAGE - 1; p++) {
        if (p < NT) copy_tile(p, p);
        cp_commit();
    }

    float c[2][4][4];
#pragma unroll
    for (int i = 0; i < 2; i++)
#pragma unroll
        for (int j = 0; j < 4; j++)
#pragma unroll
            for (int q = 0; q < 4; q++) c[i][j][q] = 0.0f;

    const int a_row = lane & 15;
    const int a_kh  = (lane >> 4) * 8;
    const int b_row = (lane & 7) + ((lane >> 4) << 3);
    const int b_kh  = ((lane >> 3) & 1) << 3;

    uint32_t aAddr[2], bAddr[2];
#pragma unroll
    for (int i = 0; i < 2; i++)
        aAddr[i] = smem_u32(&sm[(m0 + i * 16 + a_row) * KPAD + a_kh]);
#pragma unroll
    for (int j = 0; j < 2; j++)
        bAddr[j] = smem_u32(sm) + B_OFF +
                   (uint32_t)(((n0 + j * 16 + b_row) * KPAD + b_kh) * 2);

    uint32_t aF[2][2][4], bF[2][2][4];

    cp_wait<NSTAGE - 2>();
    __syncthreads();
#pragma unroll
    for (int i = 0; i < 2; i++) LDSM4(aF[0][i], aAddr[i]);
#pragma unroll
    for (int j = 0; j < 2; j++) LDSM4(bF[0][j], bAddr[j]);

    for (int kt = 0; kt < NT; kt++) {
        const uint32_t so  = (kt % NSTAGE) * STGB;
        const uint32_t so1 = ((kt + 1) % NSTAGE) * STGB;

#pragma unroll
        for (int ks = 0; ks < 4; ks++) {
            const int cb = ks & 1, nb = cb ^ 1;
            if (ks < 3) {
                const uint32_t po = so + (ks + 1) * 32;
#pragma unroll
                for (int i = 0; i < 2; i++) LDSM4(aF[nb][i], aAddr[i] + po);
#pragma unroll
                for (int j = 0; j < 2; j++) LDSM4(bF[nb][j], bAddr[j] + po);
            }
            if (ks == 1) {
                const int nk = kt + NSTAGE - 1;
                if (nk < NT) copy_tile(nk, nk % NSTAGE);
                cp_commit();
            }
            if (ks == 3) {
                cp_wait<NSTAGE - 2>();
                __syncthreads();
            }
#pragma unroll
            for (int i = 0; i < 2; i++)
#pragma unroll
                for (int jn = 0; jn < 4; jn++) {
                    const int j = jn >> 1;
                    if (jn & 1) MMA16816(c[i][jn], aF[cb][i], bF[cb][j][2], bF[cb][j][3]);
                    else        MMA16816(c[i][jn], aF[cb][i], bF[cb][j][0], bF[cb][j][1]);
                }
        }

        if (kt + 1 < NT) {
#pragma unroll
            for (int i = 0; i < 2; i++) LDSM4(aF[0][i], aAddr[i] + so1);
#pragma unroll
            for (int j = 0; j < 2; j++) LDSM4(bF[0][j], bAddr[j] + so1);
        }
    }

    // ---- epilogue ----
#pragma unroll
    for (int i = 0; i < 2; i++) {
        const int gm = brow + m0 + i * 16 + (lane >> 2);
#pragma unroll
        for (int jn = 0; jn < 4; jn++) {
            const int gc = bcol + n0 + jn * 8 + ((lane & 3) << 1);
            float2 bb = *reinterpret_cast<const float2*>(bias + gc);
#pragma unroll
            for (int rh = 0; rh < 2; rh++) {
                const int m = gm + rh * 8;
                float v0 = c[i][jn][rh * 2 + 0] + bb.x;
                float v1 = c[i][jn][rh * 2 + 1] + bb.y;
                if (SPLIT_OUT) {
                    v0 = gelu_exact(v0);
                    v1 = gelu_exact(v1);
                    *reinterpret_cast<__half2*>(outS + (size_t)m * FEAT + gc) =
                        __halves2half2(__float2half_rn(v0), __float2half_rn(v1));
                } else {
                    float2 o{v0, v1};
                    *reinterpret_cast<float2*>(outF + (size_t)m * FEAT + gc) = o;
                }
            }
        }
    }
}

// ---------------------------------------------------------------------------
extern "C" void kernel_launch(void* const* d_in, const int* in_sizes, int n_in,
                              void* d_out, int out_size)
{
    const float* x  = (const float*)d_in[0];
    const float* W1 = (const float*)d_in[1];
    const float* b1 = (const float*)d_in[2];
    const float* W2 = (const float*)d_in[3];
    const float* b2 = (const float*)d_in[4];
    float* out = (float*)d_out;

    __half *a1, *h2, *w1t, *w2t;
    cudaGetSymbolAddress((void**)&a1,  g_a1);
    cudaGetSymbolAddress((void**)&h2,  g_h2);
    cudaGetSymbolAddress((void**)&w1t, g_w1t);
    cudaGetSymbolAddress((void**)&w2t, g_w2t);

    cudaFuncSetAttribute(pre_kernel,
                         cudaFuncAttributeMaxDynamicSharedMemorySize, PRE_SMEM);
    cudaFuncSetAttribute(hmma_gemm<DIN, true>,
                         cudaFuncAttributeMaxDynamicSharedMemorySize, SMEM_BYTES);
    cudaFuncSetAttribute(hmma_gemm<FEAT, false>,
                         cudaFuncAttributeMaxDynamicSharedMemorySize, SMEM_BYTES);

    pre_kernel<<<FEATS_BLKS + 128 + 256, 256, PRE_SMEM>>>(
        x, a1, W1, w1t, W2, w2t);

    dim3 grid(FEAT / 128, B_ROWS / 64);   // (4, 64) = 256 CTAs, 2/SM
    hmma_gemm<DIN,  true ><<<grid, GT, SMEM_BYTES>>>(a1, w1t, b1, nullptr, h2);
    hmma_gemm<FEAT, false><<<grid, GT, SMEM_BYTES>>>(h2, w2t, b2, out, nullptr);
}